// round 6
// baseline (speedup 1.0000x reference)
#include <cuda_runtime.h>
#include <cuda_bf16.h>

// Problem constants
#define B 4
#define L 512
#define E 1024
#define H 128
#define NR (B * L)          // 2048 rows per tensor

__device__ __align__(16) float g_hid[2 * NR * H];
__device__ unsigned g_maxu[B];
__device__ int g_done;

typedef unsigned long long ull;

__device__ __forceinline__ float tanh_ap(float x) {
    float y;
    asm("tanh.approx.f32 %0, %1;" : "=f"(y) : "f"(x));
    return y;
}
__device__ __forceinline__ ull pack2(float lo, float hi) {
    ull r; asm("mov.b64 %0, {%1, %2};" : "=l"(r) : "f"(lo), "f"(hi)); return r;
}
__device__ __forceinline__ void unpack2(ull v, float& lo, float& hi) {
    asm("mov.b64 {%0, %1}, %2;" : "=f"(lo), "=f"(hi) : "l"(v));
}
__device__ __forceinline__ ull mul2(ull a, ull b) {
    ull r; asm("mul.rn.f32x2 %0, %1, %2;" : "=l"(r) : "l"(a), "l"(b)); return r;
}
__device__ __forceinline__ ull fma2(ull a, ull b, ull c) {
    ull r; asm("fma.rn.f32x2 %0, %1, %2, %3;" : "=l"(r) : "l"(a), "l"(b), "l"(c)); return r;
}

__device__ __forceinline__ unsigned fenc(float f) {
    unsigned b = __float_as_uint(f);
    return (b & 0x80000000u) ? ~b : (b | 0x80000000u);
}
__device__ __forceinline__ float fdec(unsigned u) {
    return (u & 0x80000000u) ? __uint_as_float(u & 0x7fffffffu)
                             : __uint_as_float(~u);
}

// ---------------------------------------------------------------------------
// Kernel 1: hid = relu(emb @ W1 + b1).
// LDS-minimized design: block = 64 rows x 32 cols, 256 threads, micro-tile
// 2 rows x 4 cols with f32x2 packed ACROSS ROWS:
//   acc_c = (acc[row0][c], acc[row1][c])
//   A read: one LDS.64 of 2 adjacent rows from kk-transposed A tile
//           (4 distinct addrs/warp -> broadcast dedup = 1 wavefront)
//   W read: pre-splatted (w,w) ull pairs in smem -> 2 LDS.128 = 2 wf
// => 3 LDS wavefronts per warp per kk vs 8 fma cycles: fma-bound.
// Double-buffered, register-staged LDG 2 tiles ahead, 1 barrier/tile.
// ---------------------------------------------------------------------------
#define KT 32
#define NT (E / KT)      // 32 tiles
#define MTR 64           // rows per block
#define MTC 32           // cols per block
#define APAD 66          // A_s row length (floats): STS near-conflict-free,
                         // LDS.64 8B-aligned (even), compute broadcast-clean
#define WPAD 34          // Ws2 row length (ulls): 16B-aligned LDS.128

__global__ __launch_bounds__(256) void gemm_relu_kernel(
    const float* __restrict__ rec, const float* __restrict__ lig,
    const float* __restrict__ W1, const float* __restrict__ b1)
{
    __shared__ __align__(16) float A_s[2][KT][APAD];   // 16.9 KB
    __shared__ __align__(16) ull   Ws2[2][KT][WPAD];   // 17.4 KB

    const int t    = threadIdx.x;
    const int bx   = blockIdx.x;
    const int row0 = (bx >> 2) * MTR;
    const int col0 = (bx & 3) * MTC;

    if (bx == 0 && t == 0) {
        g_done = 0;
#pragma unroll
        for (int b = 0; b < B; ++b) g_maxu[b] = 0u;
    }

    // compute mapping
    const int tcolg = t & 7;            // cols col0 + 4*tcolg .. +3
    const int trowg = t >> 3;           // rows row0 + 2*trowg, +1

    // A loader: 2 float4 slots: (row=ar0, kc=akc) and (row=ar0+32, same kc)
    const int ar0 = t >> 3;             // 0..31
    const int akc = (t & 7) * 4;        // 0,4,...,28
    const float* aptrA;
    const float* aptrB;
    {
        int gr = row0 + ar0;
        aptrA = (gr < NR) ? (rec + (size_t)gr * E) : (lig + (size_t)(gr - NR) * E);
        int gr2 = row0 + ar0 + 32;
        aptrB = (gr2 < NR) ? (rec + (size_t)gr2 * E) : (lig + (size_t)(gr2 - NR) * E);
    }
    // W loader: kk = t>>3 (0..31), cols wc4..+3
    const int wkk = t >> 3;
    const int wc4 = (t & 7) * 4;
    const float* wptr = W1 + (size_t)wkk * H + col0 + wc4;

    float4 aRa, aRb, wR;
    ull acc0 = 0ull, acc1 = 0ull, acc2 = 0ull, acc3 = 0ull;

#define LDG_TILE(k0)                                           \
    {                                                          \
        aRa = *(const float4*)(aptrA + (k0) + akc);            \
        aRb = *(const float4*)(aptrB + (k0) + akc);            \
        wR  = *(const float4*)(wptr + (size_t)(k0) * H);       \
    }
#define STS_TILE(buf)                                          \
    {                                                          \
        A_s[buf][akc + 0][ar0]      = aRa.x;                   \
        A_s[buf][akc + 1][ar0]      = aRa.y;                   \
        A_s[buf][akc + 2][ar0]      = aRa.z;                   \
        A_s[buf][akc + 3][ar0]      = aRa.w;                   \
        A_s[buf][akc + 0][ar0 + 32] = aRb.x;                   \
        A_s[buf][akc + 1][ar0 + 32] = aRb.y;                   \
        A_s[buf][akc + 2][ar0 + 32] = aRb.z;                   \
        A_s[buf][akc + 3][ar0 + 32] = aRb.w;                   \
        Ws2[buf][wkk][wc4 + 0] = pack2(wR.x, wR.x);            \
        Ws2[buf][wkk][wc4 + 1] = pack2(wR.y, wR.y);            \
        Ws2[buf][wkk][wc4 + 2] = pack2(wR.z, wR.z);            \
        Ws2[buf][wkk][wc4 + 3] = pack2(wR.w, wR.w);            \
    }

    LDG_TILE(0);
    STS_TILE(0);
    LDG_TILE(KT);           // tile 1 staged in regs
    __syncthreads();

    for (int kt = 0; kt < NT; ++kt) {
        int cur = kt & 1;
#pragma unroll 8
        for (int kk = 0; kk < KT; ++kk) {
            ull av = *(const ull*)&A_s[cur][kk][trowg * 2];
            ulonglong2 w01 = *(const ulonglong2*)&Ws2[cur][kk][tcolg * 4];
            ulonglong2 w23 = *(const ulonglong2*)&Ws2[cur][kk][tcolg * 4 + 2];
            acc0 = fma2(av, w01.x, acc0);
            acc1 = fma2(av, w01.y, acc1);
            acc2 = fma2(av, w23.x, acc2);
            acc3 = fma2(av, w23.y, acc3);
        }
        if (kt + 1 < NT) {
            STS_TILE(cur ^ 1);              // regs hold tile kt+1
            if (kt + 2 < NT) LDG_TILE((kt + 2) * KT);
        }
        __syncthreads();
    }

    // Epilogue: bias + relu, write 2 rows x 4 cols
    float4 bv = *(const float4*)(b1 + col0 + tcolg * 4);
    float r00, r10, r01, r11, r02, r12, r03, r13;
    unpack2(acc0, r00, r10);
    unpack2(acc1, r01, r11);
    unpack2(acc2, r02, r12);
    unpack2(acc3, r03, r13);
    float4 o0, o1;
    o0.x = fmaxf(r00 + bv.x, 0.f);  o1.x = fmaxf(r10 + bv.x, 0.f);
    o0.y = fmaxf(r01 + bv.y, 0.f);  o1.y = fmaxf(r11 + bv.y, 0.f);
    o0.z = fmaxf(r02 + bv.z, 0.f);  o1.z = fmaxf(r12 + bv.z, 0.f);
    o0.w = fmaxf(r03 + bv.w, 0.f);  o1.w = fmaxf(r13 + bv.w, 0.f);
    int gr = row0 + trowg * 2;
    *(float4*)&g_hid[(size_t)gr * H + col0 + tcolg * 4]       = o0;
    *(float4*)&g_hid[(size_t)(gr + 1) * H + col0 + tcolg * 4] = o1;
}

// ---------------------------------------------------------------------------
// Kernel 2: 256 threads (16x16), each computes a 2x2 micro-tile of S-points
// (rows ty/ty+16, cols tx/tx+16) -> 32x32 S-tile, 31x31 y-tile, block max,
// atomicMax per batch; last block finalizes sigmoid -> out.
// ---------------------------------------------------------------------------
#define TS 31
#define NTILE ((L + TS - 1) / TS)            // 17
#define NBLK  (NTILE * NTILE * B)            // 1156
#define LPAD 132

__global__ __launch_bounds__(256) void tile_max_kernel(
    const float* __restrict__ conv_w, const float* __restrict__ conv_b,
    float* __restrict__ out)
{
    __shared__ __align__(16) float r_s[32][LPAD];   // 16896 B (aliased by S)
    __shared__ __align__(16) float l_s[32][LPAD];   // 16896 B
    __shared__ __align__(16) float4 w4_s[H];        // 2 KB

    const int tx = threadIdx.x;          // 0..15
    const int ty = threadIdx.y;          // 0..15
    const int t  = ty * 16 + tx;
    const int b  = blockIdx.z;
    const int i0 = blockIdx.y * TS;
    const int j0 = blockIdx.x * TS;

    {
        int lr  = t >> 3;          // 0..31 row
        int lc4 = t & 7;           // base float4 col
        int iload = i0 - 1 + lr;
        int jload = j0 - 1 + lr;
        const float4* rsrc = (const float4*)(g_hid + (size_t)(b * L + iload) * H);
        const float4* lsrc = (const float4*)(g_hid + (size_t)(NR + b * L + jload) * H);
        bool rok = (iload >= 0 && iload < L);
        bool lok = (jload >= 0 && jload < L);
        float4 zz = make_float4(0.f, 0.f, 0.f, 0.f);
        float4* rdst = (float4*)&r_s[lr][0];
        float4* ldst = (float4*)&l_s[lr][0];
#pragma unroll
        for (int k = 0; k < 4; ++k) {
            int c4 = lc4 + 8 * k;
            rdst[c4] = rok ? rsrc[c4] : zz;
            ldst[c4] = lok ? lsrc[c4] : zz;
        }
        if (t < H) w4_s[t] = ((const float4*)conv_w)[t];   // (w00,w01,w10,w11)
    }
    __syncthreads();

    ull a00A = 0, a00B = 0, a01A = 0, a01B = 0;
    ull a10A = 0, a10B = 0, a11A = 0, a11B = 0;
    const ulonglong2* rp0 = (const ulonglong2*)&r_s[ty][0];
    const ulonglong2* rp1 = (const ulonglong2*)&r_s[ty + 16][0];
    const ulonglong2* lp0 = (const ulonglong2*)&l_s[tx][0];
    const ulonglong2* lp1 = (const ulonglong2*)&l_s[tx + 16][0];
    const ulonglong2* wp  = (const ulonglong2*)&w4_s[0];

#define COMBO(Rv, Lv, AA, BB)                                              \
    {                                                                      \
        ull pA = mul2(Rv.x, Lv.x);                                         \
        ull pB = mul2(Rv.y, Lv.y);                                         \
        float x0, x1, x2, x3;                                              \
        unpack2(pA, x0, x1);                                               \
        unpack2(pB, x2, x3);                                               \
        float t0 = tanh_ap(x0), t1 = tanh_ap(x1);                          \
        float t2 = tanh_ap(x2), t3 = tanh_ap(x3);                          \
        ull T0 = pack2(t0, t0), T1 = pack2(t1, t1);                        \
        ull T2 = pack2(t2, t2), T3 = pack2(t3, t3);                        \
        AA = fma2(T0, W0.x, AA); BB = fma2(T0, W0.y, BB);                  \
        AA = fma2(T1, W1.x, AA); BB = fma2(T1, W1.y, BB);                  \
        AA = fma2(T2, W2.x, AA); BB = fma2(T2, W2.y, BB);                  \
        AA = fma2(T3, W3.x, AA); BB = fma2(T3, W3.y, BB);                  \
    }

#pragma unroll 4
    for (int h4 = 0; h4 < H / 4; ++h4) {
        ulonglong2 R0 = rp0[h4], R1 = rp1[h4];
        ulonglong2 L0 = lp0[h4], L1 = lp1[h4];
        ulonglong2 W0 = wp[4 * h4 + 0];
        ulonglong2 W1 = wp[4 * h4 + 1];
        ulonglong2 W2 = wp[4 * h4 + 2];
        ulonglong2 W3 = wp[4 * h4 + 3];
        COMBO(R0, L0, a00A, a00B);
        COMBO(R0, L1, a01A, a01B);
        COMBO(R1, L0, a10A, a10B);
        COMBO(R1, L1, a11A, a11B);
    }
    __syncthreads();   // done reading r_s/l_s

    float4* S = (float4*)&r_s[0][0];    // 32 x 33 float4 aliases r_s
    {
        float s0, s1, s2, s3;
        unpack2(a00A, s0, s1); unpack2(a00B, s2, s3);
        S[ty * 33 + tx]             = make_float4(s0, s1, s2, s3);
        unpack2(a01A, s0, s1); unpack2(a01B, s2, s3);
        S[ty * 33 + tx + 16]        = make_float4(s0, s1, s2, s3);
        unpack2(a10A, s0, s1); unpack2(a10B, s2, s3);
        S[(ty + 16) * 33 + tx]      = make_float4(s0, s1, s2, s3);
        unpack2(a11A, s0, s1); unpack2(a11B, s2, s3);
        S[(ty + 16) * 33 + tx + 16] = make_float4(s0, s1, s2, s3);
    }
    __syncthreads();

    const float cb = conv_b[0];
    float m = -3.4e38f;
#pragma unroll
    for (int dy = 0; dy < 2; ++dy) {
#pragma unroll
        for (int dx = 0; dx < 2; ++dx) {
            int pp = ty + dy * 16, qq = tx + dx * 16;
            int p = i0 + pp, q = j0 + qq;
            if (pp < TS && qq < TS && p < L && q < L) {
                float4 a  = S[pp * 33 + qq];
                float4 bq = S[pp * 33 + qq + 1];
                float4 c  = S[(pp + 1) * 33 + qq];
                float4 d  = S[(pp + 1) * 33 + qq + 1];
                float y = cb + a.x + bq.y + c.z + d.w;
                m = fmaxf(m, y);
            }
        }
    }

#pragma unroll
    for (int o = 16; o > 0; o >>= 1)
        m = fmaxf(m, __shfl_xor_sync(0xffffffffu, m, o));
    float* red = &l_s[0][0];
    int wid = t >> 5, lid = t & 31;
    if (lid == 0) red[wid] = m;
    __syncthreads();
    if (t < 32) {
        float v = (t < 8) ? red[t] : -3.4e38f;
#pragma unroll
        for (int o = 4; o > 0; o >>= 1)
            v = fmaxf(v, __shfl_xor_sync(0xffffffffu, v, o));
        if (t == 0) {
            atomicMax(&g_maxu[b], fenc(v));
            __threadfence();
            int done = atomicAdd(&g_done, 1);
            if (done == NBLK - 1) {
#pragma unroll
                for (int bb = 0; bb < B; ++bb) {
                    unsigned u = atomicMax(&g_maxu[bb], 0u);  // atomic read
                    float mm = fdec(u);
                    out[bb] = 1.f / (1.f + expf(-mm));
                }
            }
        }
    }
}

// ---------------------------------------------------------------------------
extern "C" void kernel_launch(void* const* d_in, const int* in_sizes, int n_in,
                              void* d_out, int out_size)
{
    const float *rec = 0, *lig = 0, *W1 = 0, *b1 = 0, *conv_w = 0, *conv_b = 0;
    for (int i = 0; i < n_in; ++i) {
        int n = in_sizes[i];
        const float* p = (const float*)d_in[i];
        if (n == B * L * E)      { if (!rec) rec = p; else lig = p; }
        else if (n == E * H)     W1 = p;
        else if (n == H)         b1 = p;
        else if (n == H * 4)     conv_w = p;
        else if (n == 1)         conv_b = p;
    }
    float* out = (float*)d_out;

    gemm_relu_kernel<<<(2 * NR / MTR) * 4, 256>>>(rec, lig, W1, b1);
    dim3 g2(NTILE, NTILE, B);  // 17 x 17 x 4
    tile_max_kernel<<<g2, dim3(16, 16)>>>(conv_w, conv_b, out);
}

// round 8
// speedup vs baseline: 1.5693x; 1.5693x over previous
#include <cuda_runtime.h>
#include <cuda_bf16.h>

// Problem constants
#define B 4
#define L 512
#define E 1024
#define H 128
#define NR (B * L)          // 2048 rows per tensor

__device__ __align__(16) float g_hid[2 * NR * H];
__device__ unsigned g_maxu[B];
__device__ int g_done;

typedef unsigned long long ull;

__device__ __forceinline__ float tanh_ap(float x) {
    float y;
    asm("tanh.approx.f32 %0, %1;" : "=f"(y) : "f"(x));
    return y;
}
__device__ __forceinline__ ull pack2(float lo, float hi) {
    ull r; asm("mov.b64 %0, {%1, %2};" : "=l"(r) : "f"(lo), "f"(hi)); return r;
}
__device__ __forceinline__ void unpack2(ull v, float& lo, float& hi) {
    asm("mov.b64 {%0, %1}, %2;" : "=f"(lo), "=f"(hi) : "l"(v));
}
__device__ __forceinline__ ull mul2(ull a, ull b) {
    ull r; asm("mul.rn.f32x2 %0, %1, %2;" : "=l"(r) : "l"(a), "l"(b)); return r;
}
__device__ __forceinline__ ull fma2(ull a, ull b, ull c) {
    ull r; asm("fma.rn.f32x2 %0, %1, %2, %3;" : "=l"(r) : "l"(a), "l"(b), "l"(c)); return r;
}

__device__ __forceinline__ unsigned fenc(float f) {
    unsigned b = __float_as_uint(f);
    return (b & 0x80000000u) ? ~b : (b | 0x80000000u);
}
__device__ __forceinline__ float fdec(unsigned u) {
    return (u & 0x80000000u) ? __uint_as_float(u & 0x7fffffffu)
                             : __uint_as_float(~u);
}

// ---------------------------------------------------------------------------
// Kernel 1: hid = relu(emb @ W1 + b1).
// Block = 64 rows x 64 cols, 256 threads; warp = 8 rows x 64 cols; thread =
// 2 rows x 8 cols with f32x2 acc packed ACROSS COLS:
//   - W read: 2x LDS.128 of plain floats (col pairs contiguous -> no splat),
//     8 distinct 16B addrs/warp -> 1 wf each after broadcast dedup.
//   - A read: 2x LDS.32 broadcast; stride 36 floats -> banks (4r+kk)%32
//     distinct over the 8 rows a warp touches -> conflict-free.
//   - All STS natural row-major float4, 16B-aligned (APAD=36 -> 144B rows).
// Per kk per warp: 4 LDS wf + 8 fma2 => SM-wide ~32 wf vs ~32 fma cyc.
// K-tile 32 double-buffered, register-staged LDG, 1 barrier per tile.
// ---------------------------------------------------------------------------
#define KT 32
#define NT (E / KT)      // 32 tiles
#define APAD 36          // A_s row stride (floats): 144B, 16B-aligned
#define WPAD 68          // Ws row stride (floats): 272B, 16B-aligned

__global__ __launch_bounds__(256) void gemm_relu_kernel(
    const float* __restrict__ rec, const float* __restrict__ lig,
    const float* __restrict__ W1, const float* __restrict__ b1)
{
    __shared__ __align__(16) float A_s[2][64][APAD];   // 18.4 KB
    __shared__ __align__(16) float Ws[2][KT][WPAD];    // 17.4 KB

    const int t    = threadIdx.x;
    const int bx   = blockIdx.x;
    const int row0 = (bx >> 1) * 64;
    const int col0 = (bx & 1) * 64;

    if (bx == 0 && t == 0) {
        g_done = 0;
#pragma unroll
        for (int b = 0; b < B; ++b) g_maxu[b] = 0u;
    }

    // ---- compute mapping: warp rows, thread 2 rows x 8 cols
    const int r0 = (t >> 5) * 8 + ((t >> 3) & 3) * 2;   // block-row
    const int r1 = r0 + 1;
    const int cg = (t & 7) * 8;                         // block-col base

    // ---- loader mappings (all coalesced, row-major)
    const int lrow = t >> 2;            // 0..63 A row
    const int lac  = (t & 3) * 8;       // K offset 0,8,16,24
    const float* aptr;
    {
        int gr = row0 + lrow;
        aptr = (gr < NR) ? (rec + (size_t)gr * E + lac)
                         : (lig + (size_t)(gr - NR) * E + lac);
    }
    const int wkk = t >> 3;             // 0..31
    const int wc  = (t & 7) * 8;        // 0..56
    const float* wptr = W1 + (size_t)wkk * H + col0 + wc;

    float4 aR0, aR1, wR0, wR1;
    ull acc[2][4];
#pragma unroll
    for (int u = 0; u < 2; ++u)
#pragma unroll
        for (int v = 0; v < 4; ++v) acc[u][v] = 0ull;

#define LDG_TILE(k0)                                        \
    {                                                       \
        aR0 = *(const float4*)(aptr + (k0));                \
        aR1 = *(const float4*)(aptr + (k0) + 4);            \
        wR0 = *(const float4*)(wptr + (size_t)(k0) * H);    \
        wR1 = *(const float4*)(wptr + (size_t)(k0) * H + 4);\
    }
#define STS_TILE(buf)                                       \
    {                                                       \
        *(float4*)&A_s[buf][lrow][lac]     = aR0;           \
        *(float4*)&A_s[buf][lrow][lac + 4] = aR1;           \
        *(float4*)&Ws[buf][wkk][wc]        = wR0;           \
        *(float4*)&Ws[buf][wkk][wc + 4]    = wR1;           \
    }

    LDG_TILE(0);
    STS_TILE(0);
    LDG_TILE(KT);           // tile 1 staged in regs
    __syncthreads();

    for (int kt = 0; kt < NT; ++kt) {
        int cur = kt & 1;
#pragma unroll 8
        for (int kk = 0; kk < KT; ++kk) {
            float a0 = A_s[cur][r0][kk];     // broadcast LDS.32
            float a1 = A_s[cur][r1][kk];
            ull A0 = pack2(a0, a0);
            ull A1 = pack2(a1, a1);
            ulonglong2 wa = *(const ulonglong2*)&Ws[cur][kk][cg];
            ulonglong2 wb = *(const ulonglong2*)&Ws[cur][kk][cg + 4];
            acc[0][0] = fma2(A0, wa.x, acc[0][0]);
            acc[0][1] = fma2(A0, wa.y, acc[0][1]);
            acc[0][2] = fma2(A0, wb.x, acc[0][2]);
            acc[0][3] = fma2(A0, wb.y, acc[0][3]);
            acc[1][0] = fma2(A1, wa.x, acc[1][0]);
            acc[1][1] = fma2(A1, wa.y, acc[1][1]);
            acc[1][2] = fma2(A1, wb.x, acc[1][2]);
            acc[1][3] = fma2(A1, wb.y, acc[1][3]);
        }
        if (kt + 1 < NT) {
            STS_TILE(cur ^ 1);              // regs hold tile kt+1
            if (kt + 2 < NT) LDG_TILE((kt + 2) * KT);
        }
        __syncthreads();
    }

    // Epilogue: bias + relu, 2 rows x 8 cols (2 float4 per row)
    float4 bva = *(const float4*)(b1 + col0 + cg);
    float4 bvb = *(const float4*)(b1 + col0 + cg + 4);
#pragma unroll
    for (int u = 0; u < 2; ++u) {
        int gr = row0 + ((u == 0) ? r0 : r1);
        float c0, c1, c2, c3, c4, c5, c6, c7;
        unpack2(acc[u][0], c0, c1);
        unpack2(acc[u][1], c2, c3);
        unpack2(acc[u][2], c4, c5);
        unpack2(acc[u][3], c6, c7);
        float4 oa, ob;
        oa.x = fmaxf(c0 + bva.x, 0.f);
        oa.y = fmaxf(c1 + bva.y, 0.f);
        oa.z = fmaxf(c2 + bva.z, 0.f);
        oa.w = fmaxf(c3 + bva.w, 0.f);
        ob.x = fmaxf(c4 + bvb.x, 0.f);
        ob.y = fmaxf(c5 + bvb.y, 0.f);
        ob.z = fmaxf(c6 + bvb.z, 0.f);
        ob.w = fmaxf(c7 + bvb.w, 0.f);
        *(float4*)&g_hid[(size_t)gr * H + col0 + cg]     = oa;
        *(float4*)&g_hid[(size_t)gr * H + col0 + cg + 4] = ob;
    }
}

// ---------------------------------------------------------------------------
// Kernel 2: 256 threads (16x16), each computes a 2x2 micro-tile of S-points
// (rows ty/ty+16, cols tx/tx+16) -> 32x32 S-tile, 31x31 y-tile, block max,
// atomicMax per batch; last block finalizes sigmoid -> out.
// ---------------------------------------------------------------------------
#define TS 31
#define NTILE ((L + TS - 1) / TS)            // 17
#define NBLK  (NTILE * NTILE * B)            // 1156
#define LPAD 132

__global__ __launch_bounds__(256) void tile_max_kernel(
    const float* __restrict__ conv_w, const float* __restrict__ conv_b,
    float* __restrict__ out)
{
    __shared__ __align__(16) float r_s[32][LPAD];   // 16896 B (aliased by S)
    __shared__ __align__(16) float l_s[32][LPAD];   // 16896 B
    __shared__ __align__(16) float4 w4_s[H];        // 2 KB

    const int tx = threadIdx.x;          // 0..15
    const int ty = threadIdx.y;          // 0..15
    const int t  = ty * 16 + tx;
    const int b  = blockIdx.z;
    const int i0 = blockIdx.y * TS;
    const int j0 = blockIdx.x * TS;

    {
        int lr  = t >> 3;          // 0..31 row
        int lc4 = t & 7;           // base float4 col
        int iload = i0 - 1 + lr;
        int jload = j0 - 1 + lr;
        const float4* rsrc = (const float4*)(g_hid + (size_t)(b * L + iload) * H);
        const float4* lsrc = (const float4*)(g_hid + (size_t)(NR + b * L + jload) * H);
        bool rok = (iload >= 0 && iload < L);
        bool lok = (jload >= 0 && jload < L);
        float4 zz = make_float4(0.f, 0.f, 0.f, 0.f);
        float4* rdst = (float4*)&r_s[lr][0];
        float4* ldst = (float4*)&l_s[lr][0];
#pragma unroll
        for (int k = 0; k < 4; ++k) {
            int c4 = lc4 + 8 * k;
            rdst[c4] = rok ? rsrc[c4] : zz;
            ldst[c4] = lok ? lsrc[c4] : zz;
        }
        if (t < H) w4_s[t] = ((const float4*)conv_w)[t];   // (w00,w01,w10,w11)
    }
    __syncthreads();

    ull a00A = 0, a00B = 0, a01A = 0, a01B = 0;
    ull a10A = 0, a10B = 0, a11A = 0, a11B = 0;
    const ulonglong2* rp0 = (const ulonglong2*)&r_s[ty][0];
    const ulonglong2* rp1 = (const ulonglong2*)&r_s[ty + 16][0];
    const ulonglong2* lp0 = (const ulonglong2*)&l_s[tx][0];
    const ulonglong2* lp1 = (const ulonglong2*)&l_s[tx + 16][0];
    const ulonglong2* wp  = (const ulonglong2*)&w4_s[0];

#define COMBO(Rv, Lv, AA, BB)                                              \
    {                                                                      \
        ull pA = mul2(Rv.x, Lv.x);                                         \
        ull pB = mul2(Rv.y, Lv.y);                                         \
        float x0, x1, x2, x3;                                              \
        unpack2(pA, x0, x1);                                               \
        unpack2(pB, x2, x3);                                               \
        float t0 = tanh_ap(x0), t1 = tanh_ap(x1);                          \
        float t2 = tanh_ap(x2), t3 = tanh_ap(x3);                          \
        ull T0 = pack2(t0, t0), T1 = pack2(t1, t1);                        \
        ull T2 = pack2(t2, t2), T3 = pack2(t3, t3);                        \
        AA = fma2(T0, W0.x, AA); BB = fma2(T0, W0.y, BB);                  \
        AA = fma2(T1, W1.x, AA); BB = fma2(T1, W1.y, BB);                  \
        AA = fma2(T2, W2.x, AA); BB = fma2(T2, W2.y, BB);                  \
        AA = fma2(T3, W3.x, AA); BB = fma2(T3, W3.y, BB);                  \
    }

#pragma unroll 4
    for (int h4 = 0; h4 < H / 4; ++h4) {
        ulonglong2 R0 = rp0[h4], R1 = rp1[h4];
        ulonglong2 L0 = lp0[h4], L1 = lp1[h4];
        ulonglong2 W0 = wp[4 * h4 + 0];
        ulonglong2 W1 = wp[4 * h4 + 1];
        ulonglong2 W2 = wp[4 * h4 + 2];
        ulonglong2 W3 = wp[4 * h4 + 3];
        COMBO(R0, L0, a00A, a00B);
        COMBO(R0, L1, a01A, a01B);
        COMBO(R1, L0, a10A, a10B);
        COMBO(R1, L1, a11A, a11B);
    }
    __syncthreads();   // done reading r_s/l_s

    float4* S = (float4*)&r_s[0][0];    // 32 x 33 float4 aliases r_s
    {
        float s0, s1, s2, s3;
        unpack2(a00A, s0, s1); unpack2(a00B, s2, s3);
        S[ty * 33 + tx]             = make_float4(s0, s1, s2, s3);
        unpack2(a01A, s0, s1); unpack2(a01B, s2, s3);
        S[ty * 33 + tx + 16]        = make_float4(s0, s1, s2, s3);
        unpack2(a10A, s0, s1); unpack2(a10B, s2, s3);
        S[(ty + 16) * 33 + tx]      = make_float4(s0, s1, s2, s3);
        unpack2(a11A, s0, s1); unpack2(a11B, s2, s3);
        S[(ty + 16) * 33 + tx + 16] = make_float4(s0, s1, s2, s3);
    }
    __syncthreads();

    const float cb = conv_b[0];
    float m = -3.4e38f;
#pragma unroll
    for (int dy = 0; dy < 2; ++dy) {
#pragma unroll
        for (int dx = 0; dx < 2; ++dx) {
            int pp = ty + dy * 16, qq = tx + dx * 16;
            int p = i0 + pp, q = j0 + qq;
            if (pp < TS && qq < TS && p < L && q < L) {
                float4 a  = S[pp * 33 + qq];
                float4 bq = S[pp * 33 + qq + 1];
                float4 c  = S[(pp + 1) * 33 + qq];
                float4 d  = S[(pp + 1) * 33 + qq + 1];
                float y = cb + a.x + bq.y + c.z + d.w;
                m = fmaxf(m, y);
            }
        }
    }

#pragma unroll
    for (int o = 16; o > 0; o >>= 1)
        m = fmaxf(m, __shfl_xor_sync(0xffffffffu, m, o));
    float* red = &l_s[0][0];
    int wid = t >> 5, lid = t & 31;
    if (lid == 0) red[wid] = m;
    __syncthreads();
    if (t < 32) {
        float v = (t < 8) ? red[t] : -3.4e38f;
#pragma unroll
        for (int o = 4; o > 0; o >>= 1)
            v = fmaxf(v, __shfl_xor_sync(0xffffffffu, v, o));
        if (t == 0) {
            atomicMax(&g_maxu[b], fenc(v));
            __threadfence();
            int done = atomicAdd(&g_done, 1);
            if (done == NBLK - 1) {
#pragma unroll
                for (int bb = 0; bb < B; ++bb) {
                    unsigned u = atomicMax(&g_maxu[bb], 0u);  // atomic read
                    float mm = fdec(u);
                    out[bb] = 1.f / (1.f + expf(-mm));
                }
            }
        }
    }
}

// ---------------------------------------------------------------------------
extern "C" void kernel_launch(void* const* d_in, const int* in_sizes, int n_in,
                              void* d_out, int out_size)
{
    const float *rec = 0, *lig = 0, *W1 = 0, *b1 = 0, *conv_w = 0, *conv_b = 0;
    for (int i = 0; i < n_in; ++i) {
        int n = in_sizes[i];
        const float* p = (const float*)d_in[i];
        if (n == B * L * E)      { if (!rec) rec = p; else lig = p; }
        else if (n == E * H)     W1 = p;
        else if (n == H)         b1 = p;
        else if (n == H * 4)     conv_w = p;
        else if (n == 1)         conv_b = p;
    }
    float* out = (float*)d_out;

    gemm_relu_kernel<<<(2 * NR / 64) * 2, 256>>>(rec, lig, W1, b1);
    dim3 g2(NTILE, NTILE, B);  // 17 x 17 x 4
    tile_max_kernel<<<g2, dim3(16, 16)>>>(conv_w, conv_b, out);
}

// round 9
// speedup vs baseline: 3.0352x; 1.9341x over previous
#include <cuda_runtime.h>
#include <cuda_bf16.h>

// Problem constants
#define B 4
#define L 512
#define E 1024
#define H 128
#define NR (B * L)          // 2048 rows per tensor

__device__ __align__(16) float g_hid[2 * NR * H];
__device__ unsigned g_maxu[B];
__device__ int g_done;

typedef unsigned long long ull;

__device__ __forceinline__ float tanh_ap(float x) {
    float y;
    asm("tanh.approx.f32 %0, %1;" : "=f"(y) : "f"(x));
    return y;
}
__device__ __forceinline__ ull pack2(float lo, float hi) {
    ull r; asm("mov.b64 %0, {%1, %2};" : "=l"(r) : "f"(lo), "f"(hi)); return r;
}
__device__ __forceinline__ void unpack2(ull v, float& lo, float& hi) {
    asm("mov.b64 {%0, %1}, %2;" : "=f"(lo), "=f"(hi) : "l"(v));
}
__device__ __forceinline__ ull mul2(ull a, ull b) {
    ull r; asm("mul.rn.f32x2 %0, %1, %2;" : "=l"(r) : "l"(a), "l"(b)); return r;
}
__device__ __forceinline__ ull fma2(ull a, ull b, ull c) {
    ull r; asm("fma.rn.f32x2 %0, %1, %2, %3;" : "=l"(r) : "l"(a), "l"(b), "l"(c)); return r;
}
__device__ __forceinline__ unsigned tf32r(float x) {
    unsigned u;
    asm("cvt.rna.tf32.f32 %0, %1;" : "=r"(u) : "f"(x));
    return u;
}

__device__ __forceinline__ unsigned fenc(float f) {
    unsigned b = __float_as_uint(f);
    return (b & 0x80000000u) ? ~b : (b | 0x80000000u);
}
__device__ __forceinline__ float fdec(unsigned u) {
    return (u & 0x80000000u) ? __uint_as_float(u & 0x7fffffffu)
                             : __uint_as_float(~u);
}

// m16n8k8 tf32 MMA, f32 accumulate
__device__ __forceinline__ void mma_tf32(float c[4], const unsigned a[4],
                                         const unsigned b[2]) {
    asm volatile(
        "mma.sync.aligned.m16n8k8.row.col.f32.tf32.tf32.f32 "
        "{%0,%1,%2,%3}, {%4,%5,%6,%7}, {%8,%9}, {%0,%1,%2,%3};"
        : "+f"(c[0]), "+f"(c[1]), "+f"(c[2]), "+f"(c[3])
        : "r"(a[0]), "r"(a[1]), "r"(a[2]), "r"(a[3]),
          "r"(b[0]), "r"(b[1]));
}

// ---------------------------------------------------------------------------
// Kernel 1: hid = relu(emb @ W1 + b1) on the TENSOR pipe (tf32 mma.sync).
// Block = 64 rows x 64 cols, 256 threads, grid 128.
// Warp tile = 32 rows x 16 cols = 2 m-tiles x 2 n-tiles of m16n8k8.
// A_s[row][k] pad 36 -> fragment LDS bank 4*qr+qk all-distinct.
// W_s[k][n]  pad 72 (==8 mod 32) -> B-frag LDS bank 8*qk+qr all-distinct.
// Inputs tf32-rounded (cvt.rna) at STS. K-chunk 32 double-buffered,
// register-staged LDG, one barrier per tile.
// ---------------------------------------------------------------------------
#define KC 32
#define NTK (E / KC)     // 32 tiles
#define APAD 36
#define WPAD 72

__global__ __launch_bounds__(256) void gemm_tc_kernel(
    const float* __restrict__ rec, const float* __restrict__ lig,
    const float* __restrict__ W1, const float* __restrict__ b1)
{
    __shared__ __align__(16) float A_s[2][64][APAD];   // 18.4 KB
    __shared__ __align__(16) float W_s[2][KC][WPAD];   // 18.4 KB

    const int t    = threadIdx.x;
    const int bx   = blockIdx.x;
    const int row0 = (bx >> 1) * 64;
    const int col0 = (bx & 1) * 64;

    if (bx == 0 && t == 0) {
        g_done = 0;
#pragma unroll
        for (int b = 0; b < B; ++b) g_maxu[b] = 0u;
    }

    const int wid  = t >> 5;
    const int lane = t & 31;
    const int qr   = lane >> 2;        // 0..7
    const int qk   = lane & 3;         // 0..3
    const int wr   = (wid >> 2) * 32;  // warp row offset in block
    const int wc   = (wid & 3) * 16;   // warp col offset in block

    // loaders (coalesced, natural row-major)
    const int lar = t >> 2, lak = (t & 3) * 8;     // A: row 0..63, kc 0/8/16/24
    const float* aptr;
    {
        int gr = row0 + lar;
        aptr = (gr < NR) ? (rec + (size_t)gr * E + lak)
                         : (lig + (size_t)(gr - NR) * E + lak);
    }
    const int lwk = t >> 3, lwn = (t & 7) * 8;     // W: k 0..31, n 0/8/../56
    const float* wptr = W1 + (size_t)lwk * H + col0 + lwn;

    float4 aR0, aR1, wR0, wR1;
    float c[2][2][4];
#pragma unroll
    for (int m = 0; m < 2; ++m)
#pragma unroll
        for (int n = 0; n < 2; ++n)
#pragma unroll
            for (int i = 0; i < 4; ++i) c[m][n][i] = 0.f;

#define LDG_TILE(k0)                                         \
    {                                                        \
        aR0 = *(const float4*)(aptr + (k0));                 \
        aR1 = *(const float4*)(aptr + (k0) + 4);             \
        wR0 = *(const float4*)(wptr + (size_t)(k0) * H);     \
        wR1 = *(const float4*)(wptr + (size_t)(k0) * H + 4); \
    }
#define STS_TILE(buf)                                                     \
    {                                                                     \
        uint4 ua0 = make_uint4(tf32r(aR0.x), tf32r(aR0.y),                \
                               tf32r(aR0.z), tf32r(aR0.w));               \
        uint4 ua1 = make_uint4(tf32r(aR1.x), tf32r(aR1.y),                \
                               tf32r(aR1.z), tf32r(aR1.w));               \
        uint4 uw0 = make_uint4(tf32r(wR0.x), tf32r(wR0.y),                \
                               tf32r(wR0.z), tf32r(wR0.w));               \
        uint4 uw1 = make_uint4(tf32r(wR1.x), tf32r(wR1.y),                \
                               tf32r(wR1.z), tf32r(wR1.w));               \
        *(uint4*)&A_s[buf][lar][lak]     = ua0;                           \
        *(uint4*)&A_s[buf][lar][lak + 4] = ua1;                           \
        *(uint4*)&W_s[buf][lwk][lwn]     = uw0;                           \
        *(uint4*)&W_s[buf][lwk][lwn + 4] = uw1;                           \
    }

    LDG_TILE(0);
    STS_TILE(0);
    LDG_TILE(KC);          // tile 1 staged in regs
    __syncthreads();

    for (int kt = 0; kt < NTK; ++kt) {
        int cur = kt & 1;
#pragma unroll
        for (int ks = 0; ks < KC / 8; ++ks) {
            int k0 = ks * 8;
            unsigned a[2][4], bb[2][2];
#pragma unroll
            for (int m = 0; m < 2; ++m) {
                int r = wr + m * 16 + qr;
                a[m][0] = __float_as_uint(A_s[cur][r][k0 + qk]);
                a[m][1] = __float_as_uint(A_s[cur][r + 8][k0 + qk]);
                a[m][2] = __float_as_uint(A_s[cur][r][k0 + qk + 4]);
                a[m][3] = __float_as_uint(A_s[cur][r + 8][k0 + qk + 4]);
            }
#pragma unroll
            for (int n = 0; n < 2; ++n) {
                int nn = wc + n * 8 + qr;
                bb[n][0] = __float_as_uint(W_s[cur][k0 + qk][nn]);
                bb[n][1] = __float_as_uint(W_s[cur][k0 + qk + 4][nn]);
            }
            mma_tf32(c[0][0], a[0], bb[0]);
            mma_tf32(c[0][1], a[0], bb[1]);
            mma_tf32(c[1][0], a[1], bb[0]);
            mma_tf32(c[1][1], a[1], bb[1]);
        }
        if (kt + 1 < NTK) {
            STS_TILE(cur ^ 1);             // regs hold tile kt+1
            if (kt + 2 < NTK) LDG_TILE((kt + 2) * KC);
        }
        __syncthreads();
    }

    // Epilogue: bias + relu.  c0/c1 -> (row, col), (row, col+1);
    // c2/c3 -> (row+8, col), (row+8, col+1)
#pragma unroll
    for (int m = 0; m < 2; ++m) {
#pragma unroll
        for (int n = 0; n < 2; ++n) {
            int row = row0 + wr + m * 16 + qr;
            int col = col0 + wc + n * 8 + 2 * qk;
            float2 bv = *(const float2*)(b1 + col);
            float2 o0, o1;
            o0.x = fmaxf(c[m][n][0] + bv.x, 0.f);
            o0.y = fmaxf(c[m][n][1] + bv.y, 0.f);
            o1.x = fmaxf(c[m][n][2] + bv.x, 0.f);
            o1.y = fmaxf(c[m][n][3] + bv.y, 0.f);
            *(float2*)&g_hid[(size_t)row * H + col]       = o0;
            *(float2*)&g_hid[(size_t)(row + 8) * H + col] = o1;
        }
    }
}

// ---------------------------------------------------------------------------
// Kernel 2: 256 threads (16x16), each computes a 2x2 micro-tile of S-points
// (rows ty/ty+16, cols tx/tx+16) -> 32x32 S-tile, 31x31 y-tile, block max,
// atomicMax per batch; last block finalizes sigmoid -> out.  (unchanged)
// ---------------------------------------------------------------------------
#define TS 31
#define NTILE ((L + TS - 1) / TS)            // 17
#define NBLK  (NTILE * NTILE * B)            // 1156
#define LPAD 132

__global__ __launch_bounds__(256) void tile_max_kernel(
    const float* __restrict__ conv_w, const float* __restrict__ conv_b,
    float* __restrict__ out)
{
    __shared__ __align__(16) float r_s[32][LPAD];   // 16896 B (aliased by S)
    __shared__ __align__(16) float l_s[32][LPAD];   // 16896 B
    __shared__ __align__(16) float4 w4_s[H];        // 2 KB

    const int tx = threadIdx.x;          // 0..15
    const int ty = threadIdx.y;          // 0..15
    const int t  = ty * 16 + tx;
    const int b  = blockIdx.z;
    const int i0 = blockIdx.y * TS;
    const int j0 = blockIdx.x * TS;

    {
        int lr  = t >> 3;          // 0..31 row
        int lc4 = t & 7;           // base float4 col
        int iload = i0 - 1 + lr;
        int jload = j0 - 1 + lr;
        const float4* rsrc = (const float4*)(g_hid + (size_t)(b * L + iload) * H);
        const float4* lsrc = (const float4*)(g_hid + (size_t)(NR + b * L + jload) * H);
        bool rok = (iload >= 0 && iload < L);
        bool lok = (jload >= 0 && jload < L);
        float4 zz = make_float4(0.f, 0.f, 0.f, 0.f);
        float4* rdst = (float4*)&r_s[lr][0];
        float4* ldst = (float4*)&l_s[lr][0];
#pragma unroll
        for (int k = 0; k < 4; ++k) {
            int c4 = lc4 + 8 * k;
            rdst[c4] = rok ? rsrc[c4] : zz;
            ldst[c4] = lok ? lsrc[c4] : zz;
        }
        if (t < H) w4_s[t] = ((const float4*)conv_w)[t];   // (w00,w01,w10,w11)
    }
    __syncthreads();

    ull a00A = 0, a00B = 0, a01A = 0, a01B = 0;
    ull a10A = 0, a10B = 0, a11A = 0, a11B = 0;
    const ulonglong2* rp0 = (const ulonglong2*)&r_s[ty][0];
    const ulonglong2* rp1 = (const ulonglong2*)&r_s[ty + 16][0];
    const ulonglong2* lp0 = (const ulonglong2*)&l_s[tx][0];
    const ulonglong2* lp1 = (const ulonglong2*)&l_s[tx + 16][0];
    const ulonglong2* wp  = (const ulonglong2*)&w4_s[0];

#define COMBO(Rv, Lv, AA, BB)                                              \
    {                                                                      \
        ull pA = mul2(Rv.x, Lv.x);                                         \
        ull pB = mul2(Rv.y, Lv.y);                                         \
        float x0, x1, x2, x3;                                              \
        unpack2(pA, x0, x1);                                               \
        unpack2(pB, x2, x3);                                               \
        float t0 = tanh_ap(x0), t1 = tanh_ap(x1);                          \
        float t2 = tanh_ap(x2), t3 = tanh_ap(x3);                          \
        ull T0 = pack2(t0, t0), T1 = pack2(t1, t1);                        \
        ull T2 = pack2(t2, t2), T3 = pack2(t3, t3);                        \
        AA = fma2(T0, W0.x, AA); BB = fma2(T0, W0.y, BB);                  \
        AA = fma2(T1, W1.x, AA); BB = fma2(T1, W1.y, BB);                  \
        AA = fma2(T2, W2.x, AA); BB = fma2(T2, W2.y, BB);                  \
        AA = fma2(T3, W3.x, AA); BB = fma2(T3, W3.y, BB);                  \
    }

#pragma unroll 4
    for (int h4 = 0; h4 < H / 4; ++h4) {
        ulonglong2 R0 = rp0[h4], R1 = rp1[h4];
        ulonglong2 L0 = lp0[h4], L1 = lp1[h4];
        ulonglong2 W0 = wp[4 * h4 + 0];
        ulonglong2 W1 = wp[4 * h4 + 1];
        ulonglong2 W2 = wp[4 * h4 + 2];
        ulonglong2 W3 = wp[4 * h4 + 3];
        COMBO(R0, L0, a00A, a00B);
        COMBO(R0, L1, a01A, a01B);
        COMBO(R1, L0, a10A, a10B);
        COMBO(R1, L1, a11A, a11B);
    }
    __syncthreads();   // done reading r_s/l_s

    float4* S = (float4*)&r_s[0][0];    // 32 x 33 float4 aliases r_s
    {
        float s0, s1, s2, s3;
        unpack2(a00A, s0, s1); unpack2(a00B, s2, s3);
        S[ty * 33 + tx]             = make_float4(s0, s1, s2, s3);
        unpack2(a01A, s0, s1); unpack2(a01B, s2, s3);
        S[ty * 33 + tx + 16]        = make_float4(s0, s1, s2, s3);
        unpack2(a10A, s0, s1); unpack2(a10B, s2, s3);
        S[(ty + 16) * 33 + tx]      = make_float4(s0, s1, s2, s3);
        unpack2(a11A, s0, s1); unpack2(a11B, s2, s3);
        S[(ty + 16) * 33 + tx + 16] = make_float4(s0, s1, s2, s3);
    }
    __syncthreads();

    const float cb = conv_b[0];
    float m = -3.4e38f;
#pragma unroll
    for (int dy = 0; dy < 2; ++dy) {
#pragma unroll
        for (int dx = 0; dx < 2; ++dx) {
            int pp = ty + dy * 16, qq = tx + dx * 16;
            int p = i0 + pp, q = j0 + qq;
            if (pp < TS && qq < TS && p < L && q < L) {
                float4 a  = S[pp * 33 + qq];
                float4 bq = S[pp * 33 + qq + 1];
                float4 c  = S[(pp + 1) * 33 + qq];
                float4 d  = S[(pp + 1) * 33 + qq + 1];
                float y = cb + a.x + bq.y + c.z + d.w;
                m = fmaxf(m, y);
            }
        }
    }

#pragma unroll
    for (int o = 16; o > 0; o >>= 1)
        m = fmaxf(m, __shfl_xor_sync(0xffffffffu, m, o));
    float* red = &l_s[0][0];
    int wid = t >> 5, lid = t & 31;
    if (lid == 0) red[wid] = m;
    __syncthreads();
    if (t < 32) {
        float v = (t < 8) ? red[t] : -3.4e38f;
#pragma unroll
        for (int o = 4; o > 0; o >>= 1)
            v = fmaxf(v, __shfl_xor_sync(0xffffffffu, v, o));
        if (t == 0) {
            atomicMax(&g_maxu[b], fenc(v));
            __threadfence();
            int done = atomicAdd(&g_done, 1);
            if (done == NBLK - 1) {
#pragma unroll
                for (int bb = 0; bb < B; ++bb) {
                    unsigned u = atomicMax(&g_maxu[bb], 0u);  // atomic read
                    float mm = fdec(u);
                    out[bb] = 1.f / (1.f + expf(-mm));
                }
            }
        }
    }
}

// ---------------------------------------------------------------------------
extern "C" void kernel_launch(void* const* d_in, const int* in_sizes, int n_in,
                              void* d_out, int out_size)
{
    const float *rec = 0, *lig = 0, *W1 = 0, *b1 = 0, *conv_w = 0, *conv_b = 0;
    for (int i = 0; i < n_in; ++i) {
        int n = in_sizes[i];
        const float* p = (const float*)d_in[i];
        if (n == B * L * E)      { if (!rec) rec = p; else lig = p; }
        else if (n == E * H)     W1 = p;
        else if (n == H)         b1 = p;
        else if (n == H * 4)     conv_w = p;
        else if (n == 1)         conv_b = p;
    }
    float* out = (float*)d_out;

    gemm_tc_kernel<<<(2 * NR / 64) * 2, 256>>>(rec, lig, W1, b1);
    dim3 g2(NTILE, NTILE, B);  // 17 x 17 x 4
    tile_max_kernel<<<g2, dim3(16, 16)>>>(conv_w, conv_b, out);
}